// round 12
// baseline (speedup 1.0000x reference)
#include <cuda_runtime.h>
#include <cuda_fp16.h>
#include <mma.h>
#include <cstdint>

#define NODES 50000
#define CE    64
#define CN    256
#define KTOT  320
#define COUT  256
#define KSTEP 32
#define NKS   10
#define STAGES 3
#define NREP  4

#define AS_LD   40
#define BS_LD   264
#define AS_STAGE (128 * AS_LD)
#define BS_STAGE (32 * BS_LD)
#define SMEM_BYTES ((STAGES * AS_STAGE + STAGES * BS_STAGE) * 2)  // 81,408 B

// __device__ scratch
__device__ float  g_invD[NODES];
__device__ __half g_Acc[NREP][(size_t)NODES * CE];   // replicated fp16 accumulators
__device__ __half g_Ah[(size_t)NODES * KTOT];        // half [A/D | X]
__device__ __half g_Bh[KTOT * COUT];                 // half weights, k-major

// ---------------------------------------------------------------------------
__device__ __forceinline__ void cp_async16(void* smem, const void* gsrc, bool pred) {
    uint32_t s = (uint32_t)__cvta_generic_to_shared(smem);
    int sz = pred ? 16 : 0;
    asm volatile("cp.async.cg.shared.global [%0], [%1], 16, %2;\n"
                 :: "r"(s), "l"(gsrc), "r"(sz));
}
#define CP_COMMIT() asm volatile("cp.async.commit_group;\n" ::: "memory")
#define CP_WAIT(n)  asm volatile("cp.async.wait_group %0;\n" :: "n"(n) : "memory")

// ---------------------------------------------------------------------------
// 1) zero replicas + invD
// ---------------------------------------------------------------------------
__global__ void zero_kernel(const float* __restrict__ D) {
    int i = blockIdx.x * blockDim.x + threadIdx.x;
    if (i < NODES) g_invD[i] = __frcp_rn(__ldg(D + i));
    const int tot = NREP * NODES * 8;   // uint4 chunks (8 halves each)
    if (i < tot)
        reinterpret_cast<uint4*>(g_Acc)[i] = make_uint4(0u, 0u, 0u, 0u);
}

// 1b) weights -> half, k-major g_Bh[k][n]
__global__ void wtrans_kernel(const float* __restrict__ Wp,
                              const float* __restrict__ Ws) {
    int idx = blockIdx.x * 256 + threadIdx.x;
    if (idx >= KTOT * COUT) return;
    int k = idx >> 8, n = idx & 255;
    float v = (k < 64) ? __ldg(Wp + k * COUT + n)
                       : __ldg(Ws + (size_t)(k - 64) * COUT + n);
    g_Bh[idx] = __float2half_rn(v);
}

// 1c) X -> half into g_Ah columns [64, 320)
__global__ void convx_kernel(const float* __restrict__ X) {
    int i = blockIdx.x * blockDim.x + threadIdx.x;
    const int tot = NODES * CN / 2;
    if (i >= tot) return;
    int n = i / (CN / 2), c2 = i % (CN / 2);
    float2 v = *reinterpret_cast<const float2*>(X + (size_t)n * CN + c2 * 2);
    *reinterpret_cast<__half2*>(g_Ah + (size_t)n * KTOT + 64 + c2 * 2) =
        __floats2half2_rn(v.x, v.y);
}

// ---------------------------------------------------------------------------
// 2) scatter: 8 threads/edge, UNSCALED fp16x2 red into replica e&3.
//    All loads independent (no invD chase).
// ---------------------------------------------------------------------------
__global__ void scatter_kernel(const float4* __restrict__ ea,
                               const int* __restrict__ row_idx, int total8) {
    int i = blockIdx.x * 256 + threadIdx.x;
    if (i >= total8) return;
    int e = i >> 3, t = i & 7;
    int r = __ldg(row_idx + e);
    float4 v0 = __ldg(ea + (size_t)e * 16 + t * 2);
    float4 v1 = __ldg(ea + (size_t)e * 16 + t * 2 + 1);
    __half2 h0 = __floats2half2_rn(v0.x, v0.y);
    __half2 h1 = __floats2half2_rn(v0.z, v0.w);
    __half2 h2 = __floats2half2_rn(v1.x, v1.y);
    __half2 h3 = __floats2half2_rn(v1.z, v1.w);
    __half* dst = g_Acc[e & 3] + (size_t)r * CE + t * 8;
    asm volatile("red.global.add.noftz.v4.f16x2 [%0], {%1, %2, %3, %4};"
                 :: "l"(dst),
                    "r"(*reinterpret_cast<uint32_t*>(&h0)),
                    "r"(*reinterpret_cast<uint32_t*>(&h1)),
                    "r"(*reinterpret_cast<uint32_t*>(&h2)),
                    "r"(*reinterpret_cast<uint32_t*>(&h3))
                 : "memory");
}

// ---------------------------------------------------------------------------
// 2b) merge: sum 4 replicas in fp32, scale by invD, write g_Ah cols [0,64)
// ---------------------------------------------------------------------------
__global__ void merge_kernel() {
    int i = blockIdx.x * blockDim.x + threadIdx.x;   // uint4 (8 halves) index
    const int tot = NODES * 8;
    if (i >= tot) return;
    int n = i >> 3, c = i & 7;
    float s = g_invD[n];
    float acc[8] = {0.f, 0.f, 0.f, 0.f, 0.f, 0.f, 0.f, 0.f};
#pragma unroll
    for (int rep = 0; rep < NREP; rep++) {
        uint4 u = *reinterpret_cast<const uint4*>(
            g_Acc[rep] + (size_t)n * CE + c * 8);
        const __half2* h = reinterpret_cast<const __half2*>(&u);
#pragma unroll
        for (int j = 0; j < 4; j++) {
            float2 f = __half22float2(h[j]);
            acc[j * 2]     += f.x;
            acc[j * 2 + 1] += f.y;
        }
    }
    __half2 o[4];
#pragma unroll
    for (int j = 0; j < 4; j++)
        o[j] = __floats2half2_rn(acc[j * 2] * s, acc[j * 2 + 1] * s);
    *reinterpret_cast<uint4*>(g_Ah + (size_t)n * KTOT + c * 8) =
        *reinterpret_cast<uint4*>(o);
}

// ---------------------------------------------------------------------------
// 3) fp16 GEMM  out = relu(g_Ah @ g_Bh + bias)   (unchanged)
// ---------------------------------------------------------------------------
using namespace nvcuda;

__device__ __forceinline__ void load_stage(
    __half* As, __half* Bs, int ks, int row0, int nNodes, int tid)
{
    const int k0 = ks * KSTEP;
    {
        int r  = tid >> 2, c8 = (tid & 3) * 8;
        int gr = row0 + r;
        bool ok = gr < nNodes;
        int grc = ok ? gr : 0;
        cp_async16(As + r * AS_LD + c8,
                   g_Ah + (size_t)grc * KTOT + k0 + c8, ok);
    }
    const __half* bsrc = g_Bh + (size_t)k0 * COUT;
#pragma unroll
    for (int i = 0; i < 2; i++) {
        int j = tid + i * 512;
        int r = j >> 5, c8 = (j & 31) * 8;
        cp_async16(Bs + r * BS_LD + c8, bsrc + r * COUT + c8, true);
    }
}

typedef wmma::fragment<wmma::matrix_a, 16, 16, 16, __half, wmma::row_major> AFrag;
typedef wmma::fragment<wmma::matrix_b, 16, 16, 16, __half, wmma::row_major> BFrag;

__global__ __launch_bounds__(512, 1)
void gemm_kernel(const float* __restrict__ bp, const float* __restrict__ bs,
                 float* __restrict__ out, int nNodes) {
    extern __shared__ __half smem[];
    __half* AsBase = smem;
    __half* BsBase = smem + STAGES * AS_STAGE;

    const int tid  = threadIdx.x;
    const int warp = tid >> 5;
    const int wm   = warp >> 2;
    const int wn   = warp & 3;
    const int row0 = blockIdx.x * 128;

    float* biasf = reinterpret_cast<float*>(smem);
    for (int i = tid; i < 16 * 256; i += 512) {
        int r = i >> 8, c = i & 255;
        biasf[r * 264 + c] = __ldg(bp + c) + __ldg(bs + c);
    }
    __syncthreads();

    wmma::fragment<wmma::accumulator, 16, 16, 16, float> acc[2][4];
#pragma unroll
    for (int mi = 0; mi < 2; mi++)
#pragma unroll
        for (int ni = 0; ni < 4; ni++)
            wmma::load_matrix_sync(acc[mi][ni], biasf + wn * 64 + ni * 16,
                                   264, wmma::mem_row_major);
    __syncthreads();

#pragma unroll
    for (int s = 0; s < STAGES - 1; s++) {
        load_stage(AsBase + s * AS_STAGE, BsBase + s * BS_STAGE, s,
                   row0, nNodes, tid);
        CP_COMMIT();
    }

    for (int ks = 0; ks < NKS; ks++) {
        const int cbuf = ks % STAGES;
        const __half* As = AsBase + cbuf * AS_STAGE;
        const __half* Bs = BsBase + cbuf * BS_STAGE;

        if (ks < NKS - 1) { CP_WAIT(1); } else { CP_WAIT(0); }
        __syncthreads();

        if (ks + STAGES - 1 < NKS) {
            const int wbuf = (ks + STAGES - 1) % STAGES;
            load_stage(AsBase + wbuf * AS_STAGE, BsBase + wbuf * BS_STAGE,
                       ks + STAGES - 1, row0, nNodes, tid);
            CP_COMMIT();
        }

#pragma unroll
        for (int k16 = 0; k16 < 2; k16++) {
            AFrag af[2];
            BFrag bf[4];
#pragma unroll
            for (int mi = 0; mi < 2; mi++)
                wmma::load_matrix_sync(af[mi],
                    As + (wm * 32 + mi * 16) * AS_LD + k16 * 16, AS_LD);
#pragma unroll
            for (int ni = 0; ni < 4; ni++)
                wmma::load_matrix_sync(bf[ni],
                    Bs + (k16 * 16) * BS_LD + wn * 64 + ni * 16, BS_LD);
#pragma unroll
            for (int mi = 0; mi < 2; mi++)
#pragma unroll
                for (int ni = 0; ni < 4; ni++)
                    wmma::mma_sync(acc[mi][ni], af[mi], bf[ni], acc[mi][ni]);
        }
    }

#pragma unroll
    for (int mi = 0; mi < 2; mi++)
#pragma unroll
        for (int ni = 0; ni < 4; ni++)
#pragma unroll
            for (int t = 0; t < acc[mi][ni].num_elements; t++)
                acc[mi][ni].x[t] = fmaxf(acc[mi][ni].x[t], 0.f);

    __syncthreads();

    if (row0 + 128 <= nNodes) {
#pragma unroll
        for (int mi = 0; mi < 2; mi++)
#pragma unroll
            for (int ni = 0; ni < 4; ni++)
                wmma::store_matrix_sync(
                    out + (size_t)(row0 + wm * 32 + mi * 16) * COUT
                        + wn * 64 + ni * 16,
                    acc[mi][ni], COUT, wmma::mem_row_major);
    } else {
        float* stg = reinterpret_cast<float*>(smem);
        for (int chunk = 0; chunk < 4; chunk++) {
            __syncthreads();
            if (wm == chunk) {
#pragma unroll
                for (int mi = 0; mi < 2; mi++)
#pragma unroll
                    for (int ni = 0; ni < 4; ni++)
                        wmma::store_matrix_sync(
                            stg + (mi * 16) * 264 + wn * 64 + ni * 16,
                            acc[mi][ni], 264, wmma::mem_row_major);
            }
            __syncthreads();
            int base = row0 + chunk * 32;
            for (int idx = tid; idx < 32 * 256; idx += 512) {
                int r = idx >> 8, c = idx & 255;
                int gr = base + r;
                if (gr < nNodes)
                    out[(size_t)gr * COUT + c] = stg[r * 264 + c];
            }
        }
    }
}

// ---------------------------------------------------------------------------
extern "C" void kernel_launch(void* const* d_in, const int* in_sizes, int n_in,
                              void* d_out, int out_size) {
    const float*  D   = (const float*)d_in[0];
    const int*    row = (const int*)d_in[1];
    const float4* ea  = (const float4*)d_in[2];
    const float*  X   = (const float*)d_in[3];
    const float*  Wp  = (const float*)d_in[4];
    const float*  bp  = (const float*)d_in[5];
    const float*  Ws  = (const float*)d_in[6];
    const float*  bs  = (const float*)d_in[7];
    float* out = (float*)d_out;

    const int nNodes = in_sizes[0];
    const int E      = in_sizes[1];

    static bool attr_set = false;
    if (!attr_set) {
        cudaFuncSetAttribute(gemm_kernel,
                             cudaFuncAttributeMaxDynamicSharedMemorySize,
                             SMEM_BYTES);
        attr_set = true;
    }

    {   // zero replicas + invD
        int n = NREP * NODES * 8;
        zero_kernel<<<(n + 255) / 256, 256>>>(D);
    }
    {   // weights -> half
        int n = KTOT * COUT;
        wtrans_kernel<<<(n + 255) / 256, 256>>>(Wp, Ws);
    }
    {   // X -> half
        int n = NODES * CN / 2;
        convx_kernel<<<(n + 255) / 256, 256>>>(X);
    }
    {   // scatter (replicated fp16 atomics, no invD dependency)
        int total8 = E * 8;
        scatter_kernel<<<(total8 + 255) / 256, 256>>>(ea, row, total8);
    }
    {   // merge replicas -> g_Ah A-cols
        int n = NODES * 8;
        merge_kernel<<<(n + 255) / 256, 256>>>();
    }
    {   // fp16 GEMM
        int grid = (nNodes + 127) / 128;
        gemm_kernel<<<grid, 512, SMEM_BYTES>>>(bp, bs, out, nNodes);
    }
}

// round 13
// speedup vs baseline: 1.0427x; 1.0427x over previous
#include <cuda_runtime.h>
#include <cuda_fp16.h>
#include <mma.h>
#include <cstdint>

#define NODES 50000
#define CE    64
#define CN    256
#define KTOT  320
#define COUT  256
#define KSTEP 32
#define NKS   10
#define STAGES 3
#define NREP  4

#define AS_LD   40                       // halves per A row (32 + 8 pad)
#define BS_LD   264                      // halves per B row (256 + 8 pad)
#define AS_STAGE (64 * AS_LD)            // 2560 halves
#define BS_STAGE (32 * BS_LD)            // 8448 halves
#define SMEM_BYTES ((STAGES * AS_STAGE + STAGES * BS_STAGE) * 2)  // 66,048 B

// __device__ scratch
__device__ float  g_invD[NODES];
__device__ __half g_Acc[NREP][(size_t)NODES * CE];   // replicated fp16 accumulators
__device__ __half g_Xh[(size_t)NODES * CN];          // X in half
__device__ __half g_Bh[KTOT * COUT];                 // weights half, k-major

// ---------------------------------------------------------------------------
__device__ __forceinline__ void cp_async16(void* smem, const void* gsrc, bool pred) {
    uint32_t s = (uint32_t)__cvta_generic_to_shared(smem);
    int sz = pred ? 16 : 0;
    asm volatile("cp.async.cg.shared.global [%0], [%1], 16, %2;\n"
                 :: "r"(s), "l"(gsrc), "r"(sz));
}
#define CP_COMMIT() asm volatile("cp.async.commit_group;\n" ::: "memory")
#define CP_WAIT(n)  asm volatile("cp.async.wait_group %0;\n" :: "n"(n) : "memory")

// ---------------------------------------------------------------------------
// 1) zero replicas + invD
// ---------------------------------------------------------------------------
__global__ void zero_kernel(const float* __restrict__ D) {
    int i = blockIdx.x * blockDim.x + threadIdx.x;
    if (i < NODES) g_invD[i] = __frcp_rn(__ldg(D + i));
    const int tot = NREP * NODES * 8;   // uint4 chunks
    if (i < tot)
        reinterpret_cast<uint4*>(g_Acc)[i] = make_uint4(0u, 0u, 0u, 0u);
}

// 1b) weights -> half, k-major
__global__ void wtrans_kernel(const float* __restrict__ Wp,
                              const float* __restrict__ Ws) {
    int idx = blockIdx.x * 256 + threadIdx.x;
    if (idx >= KTOT * COUT) return;
    int k = idx >> 8, n = idx & 255;
    float v = (k < 64) ? __ldg(Wp + k * COUT + n)
                       : __ldg(Ws + (size_t)(k - 64) * COUT + n);
    g_Bh[idx] = __float2half_rn(v);
}

// 1c) X -> half
__global__ void convx_kernel(const float* __restrict__ X) {
    int i = blockIdx.x * blockDim.x + threadIdx.x;
    const int tot = NODES * CN / 2;
    if (i >= tot) return;
    float2 v = *reinterpret_cast<const float2*>(X + (size_t)i * 2);
    *reinterpret_cast<__half2*>(g_Xh + (size_t)i * 2) =
        __floats2half2_rn(v.x, v.y);
}

// ---------------------------------------------------------------------------
// 2) scatter: 8 threads/edge, unscaled fp16x2 red into replica e&3
// ---------------------------------------------------------------------------
__global__ void scatter_kernel(const float4* __restrict__ ea,
                               const int* __restrict__ row_idx, int total8) {
    int i = blockIdx.x * 256 + threadIdx.x;
    if (i >= total8) return;
    int e = i >> 3, t = i & 7;
    int r = __ldg(row_idx + e);
    float4 v0 = __ldg(ea + (size_t)e * 16 + t * 2);
    float4 v1 = __ldg(ea + (size_t)e * 16 + t * 2 + 1);
    __half2 h0 = __floats2half2_rn(v0.x, v0.y);
    __half2 h1 = __floats2half2_rn(v0.z, v0.w);
    __half2 h2 = __floats2half2_rn(v1.x, v1.y);
    __half2 h3 = __floats2half2_rn(v1.z, v1.w);
    __half* dst = g_Acc[e & 3] + (size_t)r * CE + t * 8;
    asm volatile("red.global.add.noftz.v4.f16x2 [%0], {%1, %2, %3, %4};"
                 :: "l"(dst),
                    "r"(*reinterpret_cast<uint32_t*>(&h0)),
                    "r"(*reinterpret_cast<uint32_t*>(&h1)),
                    "r"(*reinterpret_cast<uint32_t*>(&h2)),
                    "r"(*reinterpret_cast<uint32_t*>(&h3))
                 : "memory");
}

// ---------------------------------------------------------------------------
// 3) fp16 GEMM  out = relu([sum(reps)/D | X] @ Bh + bias)
//    CTA 64x256, 256 threads, 2 CTAs/SM, 3-stage cp.async (stages>=2),
//    prologue stages 0-1 built in-kernel from replicas (merge folded in).
// ---------------------------------------------------------------------------
using namespace nvcuda;

typedef wmma::fragment<wmma::matrix_a, 16, 16, 16, __half, wmma::row_major> AFrag;
typedef wmma::fragment<wmma::matrix_b, 16, 16, 16, __half, wmma::row_major> BFrag;

// B tile for chunk ks into buffer (cp.async, 4 chunks/thread)
__device__ __forceinline__ void load_B(__half* Bs, int ks, int tid) {
    const __half* bsrc = g_Bh + (size_t)ks * 32 * COUT;
#pragma unroll
    for (int i = 0; i < 4; i++) {
        int j = tid + i * 256;
        int r = j >> 5, c8 = (j & 31) * 8;
        cp_async16(Bs + r * BS_LD + c8, bsrc + r * COUT + c8, true);
    }
}

// X-sourced A tile for chunk ks (>=2), 1 chunk/thread
__device__ __forceinline__ void load_A_x(__half* As, int ks, int row0,
                                         int nNodes, int tid) {
    const int k0 = ks * KSTEP - 64;
    int r  = tid >> 2, c8 = (tid & 3) * 8;
    int gr = row0 + r;
    bool ok = gr < nNodes;
    int grc = ok ? gr : 0;
    cp_async16(As + r * AS_LD + c8, g_Xh + (size_t)grc * CN + k0 + c8, ok);
}

// replica-sourced A tile for chunk s (0 or 1): sum 4 reps fp32, scale, STS
__device__ __forceinline__ void build_A_rep(__half* As, int s, int row0,
                                            int nNodes, int tid) {
    int r  = tid >> 2, c8 = (tid & 3) * 8;
    int gr = row0 + r;
    __half2 o[4] = {__half2{}, __half2{}, __half2{}, __half2{}};
    if (gr < nNodes) {
        float acc[8] = {0.f, 0.f, 0.f, 0.f, 0.f, 0.f, 0.f, 0.f};
#pragma unroll
        for (int rep = 0; rep < NREP; rep++) {
            uint4 u = *reinterpret_cast<const uint4*>(
                g_Acc[rep] + (size_t)gr * CE + s * 32 + c8);
            const __half2* h = reinterpret_cast<const __half2*>(&u);
#pragma unroll
            for (int j = 0; j < 4; j++) {
                float2 f = __half22float2(h[j]);
                acc[j * 2]     += f.x;
                acc[j * 2 + 1] += f.y;
            }
        }
        float sc = __ldg(g_invD + gr);
#pragma unroll
        for (int j = 0; j < 4; j++)
            o[j] = __floats2half2_rn(acc[j * 2] * sc, acc[j * 2 + 1] * sc);
    }
    *reinterpret_cast<uint4*>(As + r * AS_LD + c8) =
        *reinterpret_cast<uint4*>(o);
}

__global__ __launch_bounds__(256, 2)
void gemm_kernel(const float* __restrict__ bp, const float* __restrict__ bs,
                 float* __restrict__ out, int nNodes) {
    extern __shared__ __half smem[];
    __half* AsBase = smem;
    __half* BsBase = smem + STAGES * AS_STAGE;

    const int tid  = threadIdx.x;
    const int warp = tid >> 5;
    const int wm   = warp >> 2;        // 0..1 (32 rows each)
    const int wn   = warp & 3;         // 0..3 (64 cols each)
    const int row0 = blockIdx.x * 64;

    // bias into float view of smem (overwritten by stages later)
    float* biasf = reinterpret_cast<float*>(smem);   // 16 x 264
    for (int i = tid; i < 16 * 256; i += 256) {
        int r = i >> 8, c = i & 255;
        biasf[r * 264 + c] = __ldg(bp + c) + __ldg(bs + c);
    }
    __syncthreads();

    wmma::fragment<wmma::accumulator, 16, 16, 16, float> acc[2][4];
#pragma unroll
    for (int mi = 0; mi < 2; mi++)
#pragma unroll
        for (int ni = 0; ni < 4; ni++)
            wmma::load_matrix_sync(acc[mi][ni], biasf + wn * 64 + ni * 16,
                                   264, wmma::mem_row_major);
    __syncthreads();

    // ---- prologue: stages 0 and 1 ----
    // A via replica-sum (synchronous STS; stall acceptable here), B via cp.async
    build_A_rep(AsBase + 0 * AS_STAGE, 0, row0, nNodes, tid);
    load_B(BsBase + 0 * BS_STAGE, 0, tid);
    CP_COMMIT();                                   // group for stage 0 (B)
    build_A_rep(AsBase + 1 * AS_STAGE, 1, row0, nNodes, tid);
    load_B(BsBase + 1 * BS_STAGE, 1, tid);
    CP_COMMIT();                                   // group for stage 1 (B)

    for (int ks = 0; ks < NKS; ks++) {
        const int cbuf = ks % STAGES;
        const __half* As = AsBase + cbuf * AS_STAGE;
        const __half* Bs = BsBase + cbuf * BS_STAGE;

        if (ks < NKS - 1) { CP_WAIT(1); } else { CP_WAIT(0); }
        __syncthreads();   // stage ks ready; stage ks-1 buffer reusable

        if (ks + 2 < NKS) {
            const int wbuf = (ks + 2) % STAGES;
            load_A_x(AsBase + wbuf * AS_STAGE, ks + 2, row0, nNodes, tid);
            load_B(BsBase + wbuf * BS_STAGE, ks + 2, tid);
            CP_COMMIT();
        }

#pragma unroll
        for (int k16 = 0; k16 < 2; k16++) {
            AFrag af[2];
            BFrag bf[4];
#pragma unroll
            for (int mi = 0; mi < 2; mi++)
                wmma::load_matrix_sync(af[mi],
                    As + (wm * 32 + mi * 16) * AS_LD + k16 * 16, AS_LD);
#pragma unroll
            for (int ni = 0; ni < 4; ni++)
                wmma::load_matrix_sync(bf[ni],
                    Bs + (k16 * 16) * BS_LD + wn * 64 + ni * 16, BS_LD);
#pragma unroll
            for (int mi = 0; mi < 2; mi++)
#pragma unroll
                for (int ni = 0; ni < 4; ni++)
                    wmma::mma_sync(acc[mi][ni], af[mi], bf[ni], acc[mi][ni]);
        }
    }

    // ReLU
#pragma unroll
    for (int mi = 0; mi < 2; mi++)
#pragma unroll
        for (int ni = 0; ni < 4; ni++)
#pragma unroll
            for (int t = 0; t < acc[mi][ni].num_elements; t++)
                acc[mi][ni].x[t] = fmaxf(acc[mi][ni].x[t], 0.f);

    __syncthreads();

    if (row0 + 64 <= nNodes) {
#pragma unroll
        for (int mi = 0; mi < 2; mi++)
#pragma unroll
            for (int ni = 0; ni < 4; ni++)
                wmma::store_matrix_sync(
                    out + (size_t)(row0 + wm * 32 + mi * 16) * COUT
                        + wn * 64 + ni * 16,
                    acc[mi][ni], COUT, wmma::mem_row_major);
    } else {
        // tail CTA: stage 32-row chunks through float view of smem
        float* stg = reinterpret_cast<float*>(smem);   // 32 x 264 floats
        for (int chunk = 0; chunk < 2; chunk++) {
            __syncthreads();
            if (wm == chunk) {
#pragma unroll
                for (int mi = 0; mi < 2; mi++)
#pragma unroll
                    for (int ni = 0; ni < 4; ni++)
                        wmma::store_matrix_sync(
                            stg + (mi * 16) * 264 + wn * 64 + ni * 16,
                            acc[mi][ni], 264, wmma::mem_row_major);
            }
            __syncthreads();
            int base = row0 + chunk * 32;
            for (int idx = tid; idx < 32 * 256; idx += 256) {
                int r = idx >> 8, c = idx & 255;
                int gr = base + r;
                if (gr < nNodes)
                    out[(size_t)gr * COUT + c] = stg[r * 264 + c];
            }
        }
    }
}

// ---------------------------------------------------------------------------
extern "C" void kernel_launch(void* const* d_in, const int* in_sizes, int n_in,
                              void* d_out, int out_size) {
    const float*  D   = (const float*)d_in[0];
    const int*    row = (const int*)d_in[1];
    const float4* ea  = (const float4*)d_in[2];
    const float*  X   = (const float*)d_in[3];
    const float*  Wp  = (const float*)d_in[4];
    const float*  bp  = (const float*)d_in[5];
    const float*  Ws  = (const float*)d_in[6];
    const float*  bs  = (const float*)d_in[7];
    float* out = (float*)d_out;

    const int nNodes = in_sizes[0];
    const int E      = in_sizes[1];

    static bool attr_set = false;
    if (!attr_set) {
        cudaFuncSetAttribute(gemm_kernel,
                             cudaFuncAttributeMaxDynamicSharedMemorySize,
                             SMEM_BYTES);
        attr_set = true;
    }

    {   // zero replicas + invD
        int n = NREP * NODES * 8;
        zero_kernel<<<(n + 255) / 256, 256>>>(D);
    }
    {   // weights -> half
        int n = KTOT * COUT;
        wtrans_kernel<<<(n + 255) / 256, 256>>>(Wp, Ws);
    }
    {   // X -> half
        int n = NODES * CN / 2;
        convx_kernel<<<(n + 255) / 256, 256>>>(X);
    }
    {   // scatter
        int total8 = E * 8;
        scatter_kernel<<<(total8 + 255) / 256, 256>>>(ea, row, total8);
    }
    {   // fp16 GEMM (merge folded into prologue)
        int grid = (nNodes + 63) / 64;
        gemm_kernel<<<grid, 256, SMEM_BYTES>>>(bp, bs, out, nNodes);
    }
}